// round 2
// baseline (speedup 1.0000x reference)
#include <cuda_runtime.h>
#include <math.h>

#define BB 4
#define NN 2048
#define DD 512
#define HH 8
#define DH 64
#define HD 512        // HH*DH
#define QKVC 1536     // 3*HH*DH
#define MAXREL 200

// ---- scratch (static device globals; no allocation allowed) ----
__device__ float g_mu[BB * NN];
__device__ float g_rs[BB * NN];
__device__ float g_q[BB * HH * NN * DH];
__device__ float g_k[BB * HH * NN * DH];
__device__ float g_v[BB * HH * NN * DH];
__device__ float g_attn[BB * NN * HD];

// ================= LayerNorm stats: one warp per row =================
__global__ __launch_bounds__(256) void ln_stats_kernel(const float* __restrict__ x) {
    int warp = (blockIdx.x * blockDim.x + threadIdx.x) >> 5;
    int lane = threadIdx.x & 31;
    if (warp >= BB * NN) return;
    const float4* row = reinterpret_cast<const float4*>(x + (size_t)warp * DD);
    float s = 0.f, ss = 0.f;
#pragma unroll
    for (int i = 0; i < 4; ++i) {             // 128 float4 per row / 32 lanes
        float4 v = row[lane + i * 32];
        s  += v.x + v.y + v.z + v.w;
        ss += v.x * v.x + v.y * v.y + v.z * v.z + v.w * v.w;
    }
#pragma unroll
    for (int off = 16; off; off >>= 1) {
        s  += __shfl_xor_sync(0xffffffffu, s,  off);
        ss += __shfl_xor_sync(0xffffffffu, ss, off);
    }
    if (lane == 0) {
        float mu  = s * (1.0f / DD);
        float var = ss * (1.0f / DD) - mu * mu;
        g_mu[warp] = mu;
        g_rs[warp] = rsqrtf(var + 1e-5f);
    }
}

// ================= QKV GEMM: [8192,512] x [512,1536], LN fused on A load =================
__global__ __launch_bounds__(256) void qkv_gemm_kernel(const float* __restrict__ x,
                                                       const float* __restrict__ gamma,
                                                       const float* __restrict__ beta,
                                                       const float* __restrict__ W) {
    __shared__ float As[32][65];   // [k][m]
    __shared__ float Bs[32][65];   // [k][n]
    int tid = threadIdx.x;
    int tx = tid & 15, ty = tid >> 4;
    int m0 = blockIdx.y * 64, n0 = blockIdx.x * 64;

    float acc[4][4] = {};
    for (int k0 = 0; k0 < DD; k0 += 32) {
#pragma unroll
        for (int i = 0; i < 8; ++i) {           // A tile 64x32
            int t = tid + i * 256;
            int m = t >> 5, k = t & 31;
            int r = m0 + m, kk = k0 + k;
            float v = x[(size_t)r * DD + kk];
            v = (v - g_mu[r]) * g_rs[r] * gamma[kk] + beta[kk];
            As[k][m] = v;
        }
#pragma unroll
        for (int i = 0; i < 8; ++i) {           // B tile 32x64
            int t = tid + i * 256;
            int k = t >> 6, n = t & 63;
            Bs[k][n] = W[(size_t)(k0 + k) * QKVC + n0 + n];
        }
        __syncthreads();
#pragma unroll
        for (int kk = 0; kk < 32; ++kk) {
            float a[4], b[4];
#pragma unroll
            for (int i = 0; i < 4; ++i) a[i] = As[kk][ty * 4 + i];
#pragma unroll
            for (int j = 0; j < 4; ++j) b[j] = Bs[kk][tx * 4 + j];
#pragma unroll
            for (int i = 0; i < 4; ++i)
#pragma unroll
                for (int j = 0; j < 4; ++j) acc[i][j] += a[i] * b[j];
        }
        __syncthreads();
    }
    // scatter epilogue into Q/K/V [B,H,N,d]
#pragma unroll
    for (int i = 0; i < 4; ++i) {
        int r = m0 + ty * 4 + i;
        int b = r >> 11, n = r & (NN - 1);
#pragma unroll
        for (int j = 0; j < 4; ++j) {
            int c = n0 + tx * 4 + j;
            int part = c >> 9, w = c & 511;
            int h = w >> 6, dd = w & 63;
            float* dst = (part == 0) ? g_q : ((part == 1) ? g_k : g_v);
            dst[(((size_t)(b * HH + h)) * NN + n) * DH + dd] = acc[i][j];
        }
    }
}

// ================= Flash attention: 64q x 64k tiles, online softmax =================
__global__ __launch_bounds__(256) void flash_kernel(const float* __restrict__ rel_table,
                                                    const int* __restrict__ tmask) {
    extern __shared__ float smem[];
    float (*Qs)[65] = (float(*)[65])(smem);
    float (*Ks)[65] = (float(*)[65])(smem + 64 * 65);
    float (*Vs)[65] = (float(*)[65])(smem + 2 * 64 * 65);
    float (*Ps)[65] = (float(*)[65])(smem + 3 * 64 * 65);

    int tid = threadIdx.x;
    int tx = tid & 15, ty = tid >> 4;
    int bh = blockIdx.y;              // 0..31
    int q0 = blockIdx.x * 64;
    const float* Q = g_q + (size_t)bh * NN * DH;
    const float* K = g_k + (size_t)bh * NN * DH;
    const float* V = g_v + (size_t)bh * NN * DH;

#pragma unroll
    for (int i = 0; i < 16; ++i) {    // load Q tile 64x64
        int t = tid + i * 256;
        int r = t >> 6, d = t & 63;
        Qs[r][d] = Q[(size_t)(q0 + r) * DH + d];
    }

    float o[4][4] = {};
    float mi[4], li[4];
#pragma unroll
    for (int i = 0; i < 4; ++i) { mi[i] = -INFINITY; li[i] = 0.f; }
    const float scale = 0.125f;       // 64^-0.5

    for (int k0 = 0; k0 < NN; k0 += 64) {
        __syncthreads();              // prior iter done reading Ks/Vs/Ps (and Qs visible, 1st iter)
#pragma unroll
        for (int i = 0; i < 16; ++i) {
            int t = tid + i * 256;
            int r = t >> 6, d = t & 63;
            Ks[r][d] = K[(size_t)(k0 + r) * DH + d];
            Vs[r][d] = V[(size_t)(k0 + r) * DH + d];
        }
        __syncthreads();

        // S = Q K^T (each thread 4x4)
        float s[4][4] = {};
#pragma unroll 16
        for (int d = 0; d < 64; ++d) {
            float a[4], b[4];
#pragma unroll
            for (int i = 0; i < 4; ++i) a[i] = Qs[ty * 4 + i][d];
#pragma unroll
            for (int j = 0; j < 4; ++j) b[j] = Ks[tx * 4 + j][d];
#pragma unroll
            for (int i = 0; i < 4; ++i)
#pragma unroll
                for (int j = 0; j < 4; ++j) s[i][j] += a[i] * b[j];
        }

        // scale + rel-pos bias + temporal mask
#pragma unroll
        for (int i = 0; i < 4; ++i) {
            int row = q0 + ty * 4 + i;
            const int* mrow = tmask + (size_t)row * NN + k0;
#pragma unroll
            for (int j = 0; j < 4; ++j) {
                int cc = tx * 4 + j;
                int col = k0 + cc;
                int rel = row - col;
                rel = min(max(rel, -(MAXREL - 1)), MAXREL - 1) + (MAXREL - 1);
                float v = s[i][j] * scale + __ldg(&rel_table[rel]);
                if (mrow[cc] == 0) v = -1e9f;
                s[i][j] = v;
            }
        }

        // online softmax (row groups = 16 lanes sharing ty)
#pragma unroll
        for (int i = 0; i < 4; ++i) {
            float mx = fmaxf(fmaxf(s[i][0], s[i][1]), fmaxf(s[i][2], s[i][3]));
#pragma unroll
            for (int off = 8; off; off >>= 1)
                mx = fmaxf(mx, __shfl_xor_sync(0xffffffffu, mx, off));
            float mnew = fmaxf(mi[i], mx);
            float f = __expf(mi[i] - mnew);
            float sum = 0.f;
#pragma unroll
            for (int j = 0; j < 4; ++j) { s[i][j] = __expf(s[i][j] - mnew); sum += s[i][j]; }
#pragma unroll
            for (int off = 8; off; off >>= 1)
                sum += __shfl_xor_sync(0xffffffffu, sum, off);
            li[i] = li[i] * f + sum;
            mi[i] = mnew;
#pragma unroll
            for (int j = 0; j < 4; ++j) o[i][j] *= f;
#pragma unroll
            for (int j = 0; j < 4; ++j) Ps[ty * 4 + i][tx * 4 + j] = s[i][j];
        }
        __syncthreads();

        // O += P @ V
#pragma unroll 16
        for (int kk = 0; kk < 64; ++kk) {
            float p[4], v[4];
#pragma unroll
            for (int i = 0; i < 4; ++i) p[i] = Ps[ty * 4 + i][kk];
#pragma unroll
            for (int j = 0; j < 4; ++j) v[j] = Vs[kk][tx * 4 + j];
#pragma unroll
            for (int i = 0; i < 4; ++i)
#pragma unroll
                for (int j = 0; j < 4; ++j) o[i][j] += p[i] * v[j];
        }
    }

    // finalize: write [B, N, H*d]
    int b = bh >> 3, h = bh & 7;
#pragma unroll
    for (int i = 0; i < 4; ++i) {
        int r = q0 + ty * 4 + i;
        float inv = 1.0f / li[i];
#pragma unroll
        for (int j = 0; j < 4; ++j)
            g_attn[((size_t)(b * NN + r)) * HD + h * DH + tx * 4 + j] = o[i][j] * inv;
    }
}

// ================= Out GEMM: [8192,512] x [512,512] + bias =================
__global__ __launch_bounds__(256) void out_gemm_kernel(const float* __restrict__ Wout,
                                                       const float* __restrict__ bout,
                                                       float* __restrict__ out) {
    __shared__ float As[32][65];
    __shared__ float Bs[32][65];
    int tid = threadIdx.x;
    int tx = tid & 15, ty = tid >> 4;
    int m0 = blockIdx.y * 64, n0 = blockIdx.x * 64;

    float acc[4][4] = {};
    for (int k0 = 0; k0 < HD; k0 += 32) {
#pragma unroll
        for (int i = 0; i < 8; ++i) {
            int t = tid + i * 256;
            int m = t >> 5, k = t & 31;
            As[k][m] = g_attn[(size_t)(m0 + m) * HD + k0 + k];
        }
#pragma unroll
        for (int i = 0; i < 8; ++i) {
            int t = tid + i * 256;
            int k = t >> 6, n = t & 63;
            Bs[k][n] = Wout[(size_t)(k0 + k) * DD + n0 + n];
        }
        __syncthreads();
#pragma unroll
        for (int kk = 0; kk < 32; ++kk) {
            float a[4], b[4];
#pragma unroll
            for (int i = 0; i < 4; ++i) a[i] = As[kk][ty * 4 + i];
#pragma unroll
            for (int j = 0; j < 4; ++j) b[j] = Bs[kk][tx * 4 + j];
#pragma unroll
            for (int i = 0; i < 4; ++i)
#pragma unroll
                for (int j = 0; j < 4; ++j) acc[i][j] += a[i] * b[j];
        }
        __syncthreads();
    }
#pragma unroll
    for (int i = 0; i < 4; ++i) {
        int r = m0 + ty * 4 + i;
#pragma unroll
        for (int j = 0; j < 4; ++j) {
            int c = n0 + tx * 4 + j;
            out[(size_t)r * DD + c] = acc[i][j] + bout[c];
        }
    }
}

extern "C" void kernel_launch(void* const* d_in, const int* in_sizes, int n_in,
                              void* d_out, int out_size) {
    const float* x     = (const float*)d_in[0];
    const float* gamma = (const float*)d_in[1];
    const float* beta  = (const float*)d_in[2];
    const float* Wqkv  = (const float*)d_in[3];
    const float* Wout  = (const float*)d_in[4];
    const float* bout  = (const float*)d_in[5];
    const float* rel   = (const float*)d_in[6];
    const int*   tmask = (const int*)d_in[7];
    float* out = (float*)d_out;

    ln_stats_kernel<<<(BB * NN) / 8, 256>>>(x);
    qkv_gemm_kernel<<<dim3(QKVC / 64, (BB * NN) / 64), 256>>>(x, gamma, beta, Wqkv);

    size_t smem = 4 * 64 * 65 * sizeof(float);  // 66560 B > 48K static limit
    cudaFuncSetAttribute(flash_kernel, cudaFuncAttributeMaxDynamicSharedMemorySize, (int)smem);
    flash_kernel<<<dim3(NN / 64, BB * HH), 256, smem>>>(rel, tmask);

    out_gemm_kernel<<<dim3(HD / 64, (BB * NN) / 64), 256>>>(Wout, bout, out);
}

// round 3
// speedup vs baseline: 1.1573x; 1.1573x over previous
#include <cuda_runtime.h>
#include <math.h>

#define BB 4
#define NN 2048
#define DD 512
#define HH 8
#define DH 64
#define HD 512        // HH*DH
#define QKVC 1536     // 3*HH*DH
#define MAXREL 200

// ---- scratch (static device globals; no allocation allowed) ----
__device__ float g_mu[BB * NN];
__device__ float g_rs[BB * NN];
__device__ float g_q[BB * HH * NN * DH];
__device__ float g_k[BB * HH * NN * DH];
__device__ float g_v[BB * HH * NN * DH];
__device__ float g_attn[BB * NN * HD];

// ================= LayerNorm stats: one warp per row =================
__global__ __launch_bounds__(256) void ln_stats_kernel(const float* __restrict__ x) {
    int warp = (blockIdx.x * blockDim.x + threadIdx.x) >> 5;
    int lane = threadIdx.x & 31;
    if (warp >= BB * NN) return;
    const float4* row = reinterpret_cast<const float4*>(x + (size_t)warp * DD);
    float s = 0.f, ss = 0.f;
#pragma unroll
    for (int i = 0; i < 4; ++i) {
        float4 v = row[lane + i * 32];
        s  += v.x + v.y + v.z + v.w;
        ss += v.x * v.x + v.y * v.y + v.z * v.z + v.w * v.w;
    }
#pragma unroll
    for (int off = 16; off; off >>= 1) {
        s  += __shfl_xor_sync(0xffffffffu, s,  off);
        ss += __shfl_xor_sync(0xffffffffu, ss, off);
    }
    if (lane == 0) {
        float mu  = s * (1.0f / DD);
        float var = ss * (1.0f / DD) - mu * mu;
        g_mu[warp] = mu;
        g_rs[warp] = rsqrtf(var + 1e-5f);
    }
}

// ================= QKV GEMM: 128x128 tile, 8x8 micro, LN fused on A =================
__global__ __launch_bounds__(256, 2) void qkv_gemm_kernel(const float* __restrict__ x,
                                                          const float* __restrict__ gamma,
                                                          const float* __restrict__ beta,
                                                          const float* __restrict__ W) {
    __shared__ float As[8][128];   // [k][m]
    __shared__ float Bs[8][128];   // [k][n]
    int tid = threadIdx.x;
    int tx = tid & 15, ty = tid >> 4;
    int m0 = blockIdx.y * 128, n0 = blockIdx.x * 128;

    int ar = tid >> 1, ac = (tid & 1) * 4;       // A tile: 128 rows x 8 k
    int br = tid >> 5, bc = (tid & 31) * 4;      // B tile: 8 k x 128 n
    float amu = g_mu[m0 + ar], ars = g_rs[m0 + ar];

    float acc[8][8] = {};
    float4 aN = *(const float4*)&x[(size_t)(m0 + ar) * DD + ac];
    float4 gN = *(const float4*)&gamma[ac];
    float4 eN = *(const float4*)&beta[ac];
    float4 wN = *(const float4*)&W[(size_t)br * QKVC + n0 + bc];

    for (int k0 = 0; k0 < DD; k0 += 8) {
        __syncthreads();
        float4 t;
        t.x = (aN.x - amu) * ars * gN.x + eN.x;
        t.y = (aN.y - amu) * ars * gN.y + eN.y;
        t.z = (aN.z - amu) * ars * gN.z + eN.z;
        t.w = (aN.w - amu) * ars * gN.w + eN.w;
        As[ac + 0][ar] = t.x; As[ac + 1][ar] = t.y;
        As[ac + 2][ar] = t.z; As[ac + 3][ar] = t.w;
        *(float4*)&Bs[br][bc] = wN;
        __syncthreads();
        if (k0 + 8 < DD) {
            aN = *(const float4*)&x[(size_t)(m0 + ar) * DD + k0 + 8 + ac];
            gN = *(const float4*)&gamma[k0 + 8 + ac];
            eN = *(const float4*)&beta[k0 + 8 + ac];
            wN = *(const float4*)&W[(size_t)(k0 + 8 + br) * QKVC + n0 + bc];
        }
#pragma unroll
        for (int kk = 0; kk < 8; ++kk) {
            float4 a0 = *(const float4*)&As[kk][ty * 4];
            float4 a1 = *(const float4*)&As[kk][ty * 4 + 64];
            float4 b0 = *(const float4*)&Bs[kk][tx * 4];
            float4 b1 = *(const float4*)&Bs[kk][tx * 4 + 64];
            float a[8] = {a0.x, a0.y, a0.z, a0.w, a1.x, a1.y, a1.z, a1.w};
            float b[8] = {b0.x, b0.y, b0.z, b0.w, b1.x, b1.y, b1.z, b1.w};
#pragma unroll
            for (int i = 0; i < 8; ++i)
#pragma unroll
                for (int j = 0; j < 8; ++j) acc[i][j] += a[i] * b[j];
        }
    }
    // scatter epilogue into Q/K/V [B,H,N,d], float4 stores
#pragma unroll
    for (int i = 0; i < 8; ++i) {
        int rloc = (i < 4) ? (ty * 4 + i) : (64 + ty * 4 + i - 4);
        int r = m0 + rloc;
        int b = r >> 11, n = r & (NN - 1);
#pragma unroll
        for (int ch = 0; ch < 2; ++ch) {
            int c = n0 + ch * 64 + tx * 4;
            int part = c >> 9, w = c & 511;
            int h = w >> 6, dd = w & 63;
            float* dst = (part == 0) ? g_q : ((part == 1) ? g_k : g_v);
            float4 v = make_float4(acc[i][ch * 4 + 0], acc[i][ch * 4 + 1],
                                   acc[i][ch * 4 + 2], acc[i][ch * 4 + 3]);
            *(float4*)&dst[(((size_t)(b * HH + h)) * NN + n) * DH + dd] = v;
        }
    }
}

// ================= Flash attention: 128q x 64k tiles, 8x4 micro =================
// smem: QS[64][132] d-major, KS[64][68] d-major, VS[64][68] n-major, PS[64][132] k-major
#define QS_OFF 0
#define KS_OFF 8448
#define VS_OFF 12800
#define PS_OFF 17152
#define FLASH_SMEM (25600 * 4)

__global__ __launch_bounds__(256, 1) void flash_kernel(const float* __restrict__ rel_table,
                                                       const int* __restrict__ tmask) {
    extern __shared__ float sm[];
    float* QS = sm + QS_OFF;
    float* KS = sm + KS_OFF;
    float* VS = sm + VS_OFF;
    float* PS = sm + PS_OFF;

    int tid = threadIdx.x;
    int tx = tid & 15, ty = tid >> 4;
    int ty4 = ty * 4, tx4 = tx * 4;
    int bh = blockIdx.y;
    int q0 = blockIdx.x * 128;
    const float* Q = g_q + (size_t)bh * NN * DH;
    const float* K = g_k + (size_t)bh * NN * DH;
    const float* V = g_v + (size_t)bh * NN * DH;

    // load Q tile 128x64, transposed to d-major
#pragma unroll
    for (int i = 0; i < 8; ++i) {
        int idx = tid + i * 256;
        int r = idx >> 4, d4 = (idx & 15) * 4;
        float4 v = *(const float4*)&Q[(size_t)(q0 + r) * DH + d4];
        QS[(d4 + 0) * 132 + r] = v.x;
        QS[(d4 + 1) * 132 + r] = v.y;
        QS[(d4 + 2) * 132 + r] = v.z;
        QS[(d4 + 3) * 132 + r] = v.w;
    }

    float o[8][4] = {};
    float mi[8], li[8];
#pragma unroll
    for (int i = 0; i < 8; ++i) { mi[i] = -INFINITY; li[i] = 0.f; }
    const float scale = 0.125f;

    // prefetch first K/V tile into registers
    float4 krg[4], vrg[4];
#pragma unroll
    for (int i = 0; i < 4; ++i) {
        int idx = tid + i * 256;
        int r = idx >> 4, d4 = (idx & 15) * 4;
        krg[i] = *(const float4*)&K[(size_t)r * DH + d4];
        vrg[i] = *(const float4*)&V[(size_t)r * DH + d4];
    }

    for (int k0 = 0; k0 < NN; k0 += 64) {
        __syncthreads();   // previous PV reads of VS/PS done; Q visible (iter 0)
#pragma unroll
        for (int i = 0; i < 4; ++i) {
            int idx = tid + i * 256;
            int r = idx >> 4, d4 = (idx & 15) * 4;
            KS[(d4 + 0) * 68 + r] = krg[i].x;
            KS[(d4 + 1) * 68 + r] = krg[i].y;
            KS[(d4 + 2) * 68 + r] = krg[i].z;
            KS[(d4 + 3) * 68 + r] = krg[i].w;
            *(float4*)&VS[r * 68 + d4] = vrg[i];
        }
        __syncthreads();

        // S = Q K^T
        float s[8][4] = {};
#pragma unroll 16
        for (int d = 0; d < 64; ++d) {
            float4 a0 = *(const float4*)&QS[d * 132 + ty4];
            float4 a1 = *(const float4*)&QS[d * 132 + ty4 + 64];
            float4 b  = *(const float4*)&KS[d * 68 + tx4];
            float a[8] = {a0.x, a0.y, a0.z, a0.w, a1.x, a1.y, a1.z, a1.w};
            float bb[4] = {b.x, b.y, b.z, b.w};
#pragma unroll
            for (int i = 0; i < 8; ++i)
#pragma unroll
                for (int j = 0; j < 4; ++j) s[i][j] += a[i] * bb[j];
        }

        // bias + mask + online softmax per row
#pragma unroll
        for (int i = 0; i < 8; ++i) {
            int rloc = (i < 4) ? (ty4 + i) : (64 + ty4 + i - 4);
            int r = q0 + rloc;
            int4 mm = *(const int4*)&tmask[(size_t)r * NN + k0 + tx4];
            int c0 = k0 + tx4;
            float e[4];
#pragma unroll
            for (int j = 0; j < 4; ++j) {
                int rel = r - (c0 + j);
                rel = min(max(rel, -(MAXREL - 1)), MAXREL - 1) + (MAXREL - 1);
                e[j] = s[i][j] * scale + __ldg(&rel_table[rel]);
            }
            if (mm.x == 0) e[0] = -1e9f;
            if (mm.y == 0) e[1] = -1e9f;
            if (mm.z == 0) e[2] = -1e9f;
            if (mm.w == 0) e[3] = -1e9f;

            float mx = fmaxf(fmaxf(e[0], e[1]), fmaxf(e[2], e[3]));
#pragma unroll
            for (int off = 8; off; off >>= 1)
                mx = fmaxf(mx, __shfl_xor_sync(0xffffffffu, mx, off));
            float mnew = fmaxf(mi[i], mx);
            float f = __expf(mi[i] - mnew);
            float sum = 0.f;
#pragma unroll
            for (int j = 0; j < 4; ++j) { e[j] = __expf(e[j] - mnew); sum += e[j]; }
#pragma unroll
            for (int off = 8; off; off >>= 1)
                sum += __shfl_xor_sync(0xffffffffu, sum, off);
            li[i] = li[i] * f + sum;
            mi[i] = mnew;
#pragma unroll
            for (int j = 0; j < 4; ++j) o[i][j] *= f;
            PS[(tx4 + 0) * 132 + rloc] = e[0];
            PS[(tx4 + 1) * 132 + rloc] = e[1];
            PS[(tx4 + 2) * 132 + rloc] = e[2];
            PS[(tx4 + 3) * 132 + rloc] = e[3];
        }

        // prefetch next K/V tile (LDG latency hidden behind PV)
        if (k0 + 64 < NN) {
#pragma unroll
            for (int i = 0; i < 4; ++i) {
                int idx = tid + i * 256;
                int r = idx >> 4, d4 = (idx & 15) * 4;
                krg[i] = *(const float4*)&K[(size_t)(k0 + 64 + r) * DH + d4];
                vrg[i] = *(const float4*)&V[(size_t)(k0 + 64 + r) * DH + d4];
            }
        }
        __syncthreads();   // PS visible

        // O += P @ V
#pragma unroll 16
        for (int kk = 0; kk < 64; ++kk) {
            float4 p0 = *(const float4*)&PS[kk * 132 + ty4];
            float4 p1 = *(const float4*)&PS[kk * 132 + ty4 + 64];
            float4 v  = *(const float4*)&VS[kk * 68 + tx4];
            float p[8] = {p0.x, p0.y, p0.z, p0.w, p1.x, p1.y, p1.z, p1.w};
            float vv[4] = {v.x, v.y, v.z, v.w};
#pragma unroll
            for (int i = 0; i < 8; ++i)
#pragma unroll
                for (int j = 0; j < 4; ++j) o[i][j] += p[i] * vv[j];
        }
    }

    // finalize: write [B, N, H*d]
    int b = bh >> 3, h = bh & 7;
#pragma unroll
    for (int i = 0; i < 8; ++i) {
        int rloc = (i < 4) ? (ty4 + i) : (64 + ty4 + i - 4);
        int r = q0 + rloc;
        float inv = 1.0f / li[i];
        float4 v = make_float4(o[i][0] * inv, o[i][1] * inv, o[i][2] * inv, o[i][3] * inv);
        *(float4*)&g_attn[((size_t)(b * NN + r)) * HD + h * DH + tx4] = v;
    }
}

// ================= Out GEMM: 128x128 tile, 8x8 micro, + bias =================
__global__ __launch_bounds__(256, 2) void out_gemm_kernel(const float* __restrict__ Wout,
                                                          const float* __restrict__ bout,
                                                          float* __restrict__ out) {
    __shared__ float As[8][128];
    __shared__ float Bs[8][128];
    int tid = threadIdx.x;
    int tx = tid & 15, ty = tid >> 4;
    int m0 = blockIdx.y * 128, n0 = blockIdx.x * 128;

    int ar = tid >> 1, ac = (tid & 1) * 4;
    int br = tid >> 5, bc = (tid & 31) * 4;

    float acc[8][8] = {};
    float4 aN = *(const float4*)&g_attn[(size_t)(m0 + ar) * HD + ac];
    float4 wN = *(const float4*)&Wout[(size_t)br * DD + n0 + bc];

    for (int k0 = 0; k0 < HD; k0 += 8) {
        __syncthreads();
        As[ac + 0][ar] = aN.x; As[ac + 1][ar] = aN.y;
        As[ac + 2][ar] = aN.z; As[ac + 3][ar] = aN.w;
        *(float4*)&Bs[br][bc] = wN;
        __syncthreads();
        if (k0 + 8 < HD) {
            aN = *(const float4*)&g_attn[(size_t)(m0 + ar) * HD + k0 + 8 + ac];
            wN = *(const float4*)&Wout[(size_t)(k0 + 8 + br) * DD + n0 + bc];
        }
#pragma unroll
        for (int kk = 0; kk < 8; ++kk) {
            float4 a0 = *(const float4*)&As[kk][ty * 4];
            float4 a1 = *(const float4*)&As[kk][ty * 4 + 64];
            float4 b0 = *(const float4*)&Bs[kk][tx * 4];
            float4 b1 = *(const float4*)&Bs[kk][tx * 4 + 64];
            float a[8] = {a0.x, a0.y, a0.z, a0.w, a1.x, a1.y, a1.z, a1.w};
            float b[8] = {b0.x, b0.y, b0.z, b0.w, b1.x, b1.y, b1.z, b1.w};
#pragma unroll
            for (int i = 0; i < 8; ++i)
#pragma unroll
                for (int j = 0; j < 8; ++j) acc[i][j] += a[i] * b[j];
        }
    }
#pragma unroll
    for (int i = 0; i < 8; ++i) {
        int rloc = (i < 4) ? (ty * 4 + i) : (64 + ty * 4 + i - 4);
        int r = m0 + rloc;
#pragma unroll
        for (int ch = 0; ch < 2; ++ch) {
            int c = n0 + ch * 64 + tx * 4;
            float4 bo = *(const float4*)&bout[c];
            float4 v = make_float4(acc[i][ch * 4 + 0] + bo.x, acc[i][ch * 4 + 1] + bo.y,
                                   acc[i][ch * 4 + 2] + bo.z, acc[i][ch * 4 + 3] + bo.w);
            *(float4*)&out[(size_t)r * DD + c] = v;
        }
    }
}

extern "C" void kernel_launch(void* const* d_in, const int* in_sizes, int n_in,
                              void* d_out, int out_size) {
    const float* x     = (const float*)d_in[0];
    const float* gamma = (const float*)d_in[1];
    const float* beta  = (const float*)d_in[2];
    const float* Wqkv  = (const float*)d_in[3];
    const float* Wout  = (const float*)d_in[4];
    const float* bout  = (const float*)d_in[5];
    const float* rel   = (const float*)d_in[6];
    const int*   tmask = (const int*)d_in[7];
    float* out = (float*)d_out;

    ln_stats_kernel<<<(BB * NN) / 8, 256>>>(x);
    qkv_gemm_kernel<<<dim3(QKVC / 128, (BB * NN) / 128), 256>>>(x, gamma, beta, Wqkv);

    cudaFuncSetAttribute(flash_kernel, cudaFuncAttributeMaxDynamicSharedMemorySize, FLASH_SMEM);
    flash_kernel<<<dim3(NN / 128, BB * HH), 256, FLASH_SMEM>>>(rel, tmask);

    out_gemm_kernel<<<dim3(DD / 128, (BB * NN) / 128), 256>>>(Wout, bout, out);
}

// round 5
// speedup vs baseline: 2.0083x; 1.7353x over previous
#include <cuda_runtime.h>
#include <math.h>
#include <stdint.h>

#define BB 4
#define NN 2048
#define DD 512
#define HH 8
#define DH 64
#define HD 512        // HH*DH
#define QKVC 1536     // 3*HH*DH
#define MAXREL 200

// ---- scratch (static device globals; no allocation allowed) ----
__device__ float g_mu[BB * NN];
__device__ float g_rs[BB * NN];
__device__ float g_q[BB * HH * NN * DH];    // [b,h,n,d]  (tf32-rounded, pre-scaled)
__device__ float g_k[BB * HH * NN * DH];    // [b,h,n,d]  (tf32-rounded)
__device__ float g_vT[BB * HH * DH * NN];   // [b,h,d,n]  (tf32-rounded, transposed)
__device__ float g_attn[BB * NN * HD];

__device__ __forceinline__ float to_tf32(float x) {
    float r;
    asm("cvt.rna.tf32.f32 %0, %1;" : "=f"(r) : "f"(x));
    return r;
}

__device__ __forceinline__ void cp16(uint32_t s, const void* g) {
    asm volatile("cp.async.ca.shared.global [%0], [%1], 16;" :: "r"(s), "l"(g));
}
#define CP_COMMIT()  asm volatile("cp.async.commit_group;")
#define CP_WAIT(N)   asm volatile("cp.async.wait_group %0;" :: "n"(N))

#define MMA_TF32(d, a0,a1,a2,a3, b0,b1)                                        \
    asm volatile("mma.sync.aligned.m16n8k8.row.col.f32.tf32.tf32.f32 "         \
        "{%0,%1,%2,%3},{%4,%5,%6,%7},{%8,%9},{%0,%1,%2,%3};"                   \
        : "+f"((d)[0]), "+f"((d)[1]), "+f"((d)[2]), "+f"((d)[3])               \
        : "r"(a0), "r"(a1), "r"(a2), "r"(a3), "r"(b0), "r"(b1))

// ================= LayerNorm stats: one warp per row =================
__global__ __launch_bounds__(256) void ln_stats_kernel(const float* __restrict__ x) {
    int warp = (blockIdx.x * blockDim.x + threadIdx.x) >> 5;
    int lane = threadIdx.x & 31;
    if (warp >= BB * NN) return;
    const float4* row = reinterpret_cast<const float4*>(x + (size_t)warp * DD);
    float s = 0.f, ss = 0.f;
#pragma unroll
    for (int i = 0; i < 4; ++i) {
        float4 v = row[lane + i * 32];
        s  += v.x + v.y + v.z + v.w;
        ss += v.x * v.x + v.y * v.y + v.z * v.z + v.w * v.w;
    }
#pragma unroll
    for (int off = 16; off; off >>= 1) {
        s  += __shfl_xor_sync(0xffffffffu, s,  off);
        ss += __shfl_xor_sync(0xffffffffu, ss, off);
    }
    if (lane == 0) {
        float mu  = s * (1.0f / DD);
        float var = ss * (1.0f / DD) - mu * mu;
        g_mu[warp] = mu;
        g_rs[warp] = rsqrtf(var + 1e-5f);
    }
}

// ================= QKV GEMM: 128x128 tile, 8x8 micro, LN fused on A =================
__global__ __launch_bounds__(256, 2) void qkv_gemm_kernel(const float* __restrict__ x,
                                                          const float* __restrict__ gamma,
                                                          const float* __restrict__ beta,
                                                          const float* __restrict__ W) {
    __shared__ float As[8][128];
    __shared__ float Bs[8][128];
    int tid = threadIdx.x;
    int tx = tid & 15, ty = tid >> 4;
    int m0 = blockIdx.y * 128, n0 = blockIdx.x * 128;

    int ar = tid >> 1, ac = (tid & 1) * 4;
    int br = tid >> 5, bc = (tid & 31) * 4;
    float amu = g_mu[m0 + ar], ars = g_rs[m0 + ar];

    float acc[8][8] = {};
    float4 aN = *(const float4*)&x[(size_t)(m0 + ar) * DD + ac];
    float4 gN = *(const float4*)&gamma[ac];
    float4 eN = *(const float4*)&beta[ac];
    float4 wN = *(const float4*)&W[(size_t)br * QKVC + n0 + bc];

    for (int k0 = 0; k0 < DD; k0 += 8) {
        __syncthreads();
        float4 t;
        t.x = (aN.x - amu) * ars * gN.x + eN.x;
        t.y = (aN.y - amu) * ars * gN.y + eN.y;
        t.z = (aN.z - amu) * ars * gN.z + eN.z;
        t.w = (aN.w - amu) * ars * gN.w + eN.w;
        As[ac + 0][ar] = t.x; As[ac + 1][ar] = t.y;
        As[ac + 2][ar] = t.z; As[ac + 3][ar] = t.w;
        *(float4*)&Bs[br][bc] = wN;
        __syncthreads();
        if (k0 + 8 < DD) {
            aN = *(const float4*)&x[(size_t)(m0 + ar) * DD + k0 + 8 + ac];
            gN = *(const float4*)&gamma[k0 + 8 + ac];
            eN = *(const float4*)&beta[k0 + 8 + ac];
            wN = *(const float4*)&W[(size_t)(k0 + 8 + br) * QKVC + n0 + bc];
        }
#pragma unroll
        for (int kk = 0; kk < 8; ++kk) {
            float4 a0 = *(const float4*)&As[kk][ty * 4];
            float4 a1 = *(const float4*)&As[kk][ty * 4 + 64];
            float4 b0 = *(const float4*)&Bs[kk][tx * 4];
            float4 b1 = *(const float4*)&Bs[kk][tx * 4 + 64];
            float a[8] = {a0.x, a0.y, a0.z, a0.w, a1.x, a1.y, a1.z, a1.w};
            float b[8] = {b0.x, b0.y, b0.z, b0.w, b1.x, b1.y, b1.z, b1.w};
#pragma unroll
            for (int i = 0; i < 8; ++i)
#pragma unroll
                for (int j = 0; j < 8; ++j) acc[i][j] += a[i] * b[j];
        }
    }
    // scatter epilogue: Q (scaled, tf32) / K (tf32) -> [B,H,N,d]; V (tf32) -> [B,H,d,N]
#pragma unroll
    for (int i = 0; i < 8; ++i) {
        int rloc = (i < 4) ? (ty * 4 + i) : (64 + ty * 4 + i - 4);
        int r = m0 + rloc;
        int b = r >> 11, n = r & (NN - 1);
#pragma unroll
        for (int ch = 0; ch < 2; ++ch) {
            int c = n0 + ch * 64 + tx * 4;
            int part = c >> 9, w = c & 511;
            int h = w >> 6, dd = w & 63;
            size_t bh = (size_t)(b * HH + h);
            if (part == 0) {
                float4 v = make_float4(to_tf32(acc[i][ch*4+0] * 0.125f), to_tf32(acc[i][ch*4+1] * 0.125f),
                                       to_tf32(acc[i][ch*4+2] * 0.125f), to_tf32(acc[i][ch*4+3] * 0.125f));
                *(float4*)&g_q[(bh * NN + n) * DH + dd] = v;
            } else if (part == 1) {
                float4 v = make_float4(to_tf32(acc[i][ch*4+0]), to_tf32(acc[i][ch*4+1]),
                                       to_tf32(acc[i][ch*4+2]), to_tf32(acc[i][ch*4+3]));
                *(float4*)&g_k[(bh * NN + n) * DH + dd] = v;
            } else {
#pragma unroll
                for (int j = 0; j < 4; ++j)
                    g_vT[(bh * DH + dd + j) * NN + n] = to_tf32(acc[i][ch*4+j]);
            }
        }
    }
}

// ================= Flash attention with tf32 mma.sync =================
// smem (floats, stride 68): QS[128][68], KS[2][64][68], VSt[2][64][68], PS[128][68]
// QS/PS row-major [qrow][d|k]; KS row-major [keyrow][d]; VS [d][keyrow]
#define FS_QS   0
#define FS_KS   8704
#define FS_VS   13056
#define FS_STG  8704        // stage stride (KS+VS pair)
#define FS_PS   26112
#define FS_TOT  34816
#define FLASH_SMEM (FS_TOT * 4)
#define NT_TILES (NN / 64)

__global__ __launch_bounds__(256, 1) void flash_mma_kernel(const float* __restrict__ rel_table,
                                                           const int* __restrict__ tmask) {
    extern __shared__ float sm[];
    uint32_t smb = (uint32_t)__cvta_generic_to_shared(sm);

    int tid  = threadIdx.x;
    int lane = tid & 31, wid = tid >> 5;
    int g   = lane >> 2;          // groupID 0..7
    int tig = lane & 3;           // thread-in-group 0..3
    int bh = blockIdx.y;
    int q0 = blockIdx.x * 128;
    const float* Q  = g_q  + (size_t)bh * NN * DH;
    const float* K  = g_k  + (size_t)bh * NN * DH;
    const float* Vt = g_vT + (size_t)bh * DH * NN;

    // per-pass coords: 256 threads cover 64x64 floats (16 threads/row of 64)
    int lr = tid >> 4;            // 0..15
    int lc = (tid & 15) * 4;      // 0..60

    // ---- issue Q tile (128x64) + first K/V tile via cp.async (full coverage) ----
#pragma unroll
    for (int i = 0; i < 8; ++i) {   // Q: 128 rows
        int r = lr + i * 16;
        cp16(smb + (FS_QS + r * 68 + lc) * 4, Q + (size_t)(q0 + r) * DH + lc);
    }
#pragma unroll
    for (int i = 0; i < 4; ++i) {   // K tile 0: 64 rows [keyrow][d]
        int r = lr + i * 16;
        cp16(smb + (FS_KS + r * 68 + lc) * 4, K + (size_t)r * DH + lc);
    }
#pragma unroll
    for (int i = 0; i < 4; ++i) {   // V tile 0: [d][keyrow]
        int r = lr + i * 16;
        cp16(smb + (FS_VS + r * 68 + lc) * 4, Vt + (size_t)r * NN + lc);
    }
    CP_COMMIT();

    float oa[8][4] = {};
    float mi[2] = {-INFINITY, -INFINITY};
    float li[2] = {0.f, 0.f};

    const int m_row = wid * 16 + g;          // local q-row (lower of pair)
    const float* qb = sm + FS_QS + m_row * 68 + tig;

    for (int t = 0; t < NT_TILES; ++t) {
        int cur = t & 1;
        int k0 = t * 64;
        if (t > 0) __syncthreads();          // prev iter done reading the buffer we overwrite
        if (t + 1 < NT_TILES) {
            int nxt = cur ^ 1;
#pragma unroll
            for (int i = 0; i < 4; ++i) {
                int r = lr + i * 16;
                cp16(smb + (FS_KS + nxt * FS_STG + r * 68 + lc) * 4,
                     K + (size_t)(k0 + 64 + r) * DH + lc);
            }
#pragma unroll
            for (int i = 0; i < 4; ++i) {
                int r = lr + i * 16;
                cp16(smb + (FS_VS + nxt * FS_STG + r * 68 + lc) * 4,
                     Vt + (size_t)r * NN + k0 + 64 + lc);
            }
            CP_COMMIT();
            CP_WAIT(1);
        } else {
            CP_WAIT(0);
        }
        __syncthreads();                     // tile t visible to all

        const float* kb = sm + FS_KS + cur * FS_STG + g * 68 + tig;
        const float* vb = sm + FS_VS + cur * FS_STG + g * 68 + tig;

        // ---- S = Q K^T : 8 ksteps x 8 ntiles of m16n8k8 ----
        float sa[8][4] = {};
#pragma unroll
        for (int ks = 0; ks < 8; ++ks) {
            uint32_t a0 = __float_as_uint(qb[ks * 8]);
            uint32_t a1 = __float_as_uint(qb[8 * 68 + ks * 8]);
            uint32_t a2 = __float_as_uint(qb[ks * 8 + 4]);
            uint32_t a3 = __float_as_uint(qb[8 * 68 + ks * 8 + 4]);
#pragma unroll
            for (int nt = 0; nt < 8; ++nt) {
                uint32_t b0 = __float_as_uint(kb[nt * 8 * 68 + ks * 8]);
                uint32_t b1 = __float_as_uint(kb[nt * 8 * 68 + ks * 8 + 4]);
                MMA_TF32(sa[nt], a0, a1, a2, a3, b0, b1);
            }
        }

        // ---- bias + mask + online softmax (rows m_row, m_row+8) ----
#pragma unroll
        for (int ri = 0; ri < 2; ++ri) {
            int rl = m_row + ri * 8;
            int rg = q0 + rl;
            const int2* mp = (const int2*)(tmask + (size_t)rg * NN + k0);
            float mloc = -INFINITY;
#pragma unroll
            for (int nt = 0; nt < 8; ++nt) {
                int cc = nt * 8 + 2 * tig;
                int2 mm = mp[nt * 4 + tig];
                int cg = k0 + cc;
                int rel0 = min(max(rg - cg,     -(MAXREL - 1)), MAXREL - 1) + (MAXREL - 1);
                int rel1 = min(max(rg - cg - 1, -(MAXREL - 1)), MAXREL - 1) + (MAXREL - 1);
                float v0 = sa[nt][ri * 2 + 0] + __ldg(&rel_table[rel0]);
                float v1 = sa[nt][ri * 2 + 1] + __ldg(&rel_table[rel1]);
                v0 = (mm.x == 0) ? -1e9f : v0;
                v1 = (mm.y == 0) ? -1e9f : v1;
                sa[nt][ri * 2 + 0] = v0;
                sa[nt][ri * 2 + 1] = v1;
                mloc = fmaxf(mloc, fmaxf(v0, v1));
            }
            mloc = fmaxf(mloc, __shfl_xor_sync(0xffffffffu, mloc, 1));
            mloc = fmaxf(mloc, __shfl_xor_sync(0xffffffffu, mloc, 2));
            float mnew = fmaxf(mi[ri], mloc);
            float f = __expf(mi[ri] - mnew);
            float sum = 0.f;
            float2* psr = (float2*)(sm + FS_PS + rl * 68 + 2 * tig);
#pragma unroll
            for (int nt = 0; nt < 8; ++nt) {
                float e0 = to_tf32(__expf(sa[nt][ri * 2 + 0] - mnew));
                float e1 = to_tf32(__expf(sa[nt][ri * 2 + 1] - mnew));
                sum += e0 + e1;
                psr[nt * 4] = make_float2(e0, e1);
            }
            sum += __shfl_xor_sync(0xffffffffu, sum, 1);
            sum += __shfl_xor_sync(0xffffffffu, sum, 2);
            li[ri] = li[ri] * f + sum;
            mi[ri] = mnew;
#pragma unroll
            for (int nt = 0; nt < 8; ++nt) {
                oa[nt][ri * 2 + 0] *= f;
                oa[nt][ri * 2 + 1] *= f;
            }
        }
        __syncwarp();                        // PS rows are warp-private; warp-level fence suffices

        // ---- O += P V : k = seq(64), n = d(64) ----
        const float* pb = sm + FS_PS + m_row * 68 + tig;
#pragma unroll
        for (int ks = 0; ks < 8; ++ks) {
            uint32_t a0 = __float_as_uint(pb[ks * 8]);
            uint32_t a1 = __float_as_uint(pb[8 * 68 + ks * 8]);
            uint32_t a2 = __float_as_uint(pb[ks * 8 + 4]);
            uint32_t a3 = __float_as_uint(pb[8 * 68 + ks * 8 + 4]);
#pragma unroll
            for (int nt = 0; nt < 8; ++nt) {
                uint32_t b0 = __float_as_uint(vb[nt * 8 * 68 + ks * 8]);
                uint32_t b1 = __float_as_uint(vb[nt * 8 * 68 + ks * 8 + 4]);
                MMA_TF32(oa[nt], a0, a1, a2, a3, b0, b1);
            }
        }
    }

    // ---- finalize: write [B, N, H*d] ----
    int b = bh >> 3, h = bh & 7;
    float inv0 = 1.0f / li[0], inv1 = 1.0f / li[1];
#pragma unroll
    for (int nt = 0; nt < 8; ++nt) {
        int col = h * DH + nt * 8 + 2 * tig;
        int r0 = q0 + m_row;
        *(float2*)&g_attn[((size_t)(b * NN + r0)) * HD + col] =
            make_float2(oa[nt][0] * inv0, oa[nt][1] * inv0);
        *(float2*)&g_attn[((size_t)(b * NN + r0 + 8)) * HD + col] =
            make_float2(oa[nt][2] * inv1, oa[nt][3] * inv1);
    }
}

// ================= Out GEMM: 128x128 tile, 8x8 micro, + bias =================
__global__ __launch_bounds__(256, 2) void out_gemm_kernel(const float* __restrict__ Wout,
                                                          const float* __restrict__ bout,
                                                          float* __restrict__ out) {
    __shared__ float As[8][128];
    __shared__ float Bs[8][128];
    int tid = threadIdx.x;
    int tx = tid & 15, ty = tid >> 4;
    int m0 = blockIdx.y * 128, n0 = blockIdx.x * 128;

    int ar = tid >> 1, ac = (tid & 1) * 4;
    int br = tid >> 5, bc = (tid & 31) * 4;

    float acc[8][8] = {};
    float4 aN = *(const float4*)&g_attn[(size_t)(m0 + ar) * HD + ac];
    float4 wN = *(const float4*)&Wout[(size_t)br * DD + n0 + bc];

    for (int k0 = 0; k0 < HD; k0 += 8) {
        __syncthreads();
        As[ac + 0][ar] = aN.x; As[ac + 1][ar] = aN.y;
        As[ac + 2][ar] = aN.z; As[ac + 3][ar] = aN.w;
        *(float4*)&Bs[br][bc] = wN;
        __syncthreads();
        if (k0 + 8 < HD) {
            aN = *(const float4*)&g_attn[(size_t)(m0 + ar) * HD + k0 + 8 + ac];
            wN = *(const float4*)&Wout[(size_t)(k0 + 8 + br) * DD + n0 + bc];
        }
#pragma unroll
        for (int kk = 0; kk < 8; ++kk) {
            float4 a0 = *(const float4*)&As[kk][ty * 4];
            float4 a1 = *(const float4*)&As[kk][ty * 4 + 64];
            float4 b0 = *(const float4*)&Bs[kk][tx * 4];
            float4 b1 = *(const float4*)&Bs[kk][tx * 4 + 64];
            float a[8] = {a0.x, a0.y, a0.z, a0.w, a1.x, a1.y, a1.z, a1.w};
            float b[8] = {b0.x, b0.y, b0.z, b0.w, b1.x, b1.y, b1.z, b1.w};
#pragma unroll
            for (int i = 0; i < 8; ++i)
#pragma unroll
                for (int j = 0; j < 8; ++j) acc[i][j] += a[i] * b[j];
        }
    }
#pragma unroll
    for (int i = 0; i < 8; ++i) {
        int rloc = (i < 4) ? (ty * 4 + i) : (64 + ty * 4 + i - 4);
        int r = m0 + rloc;
#pragma unroll
        for (int ch = 0; ch < 2; ++ch) {
            int c = n0 + ch * 64 + tx * 4;
            float4 bo = *(const float4*)&bout[c];
            float4 v = make_float4(acc[i][ch * 4 + 0] + bo.x, acc[i][ch * 4 + 1] + bo.y,
                                   acc[i][ch * 4 + 2] + bo.z, acc[i][ch * 4 + 3] + bo.w);
            *(float4*)&out[(size_t)r * DD + c] = v;
        }
    }
}

extern "C" void kernel_launch(void* const* d_in, const int* in_sizes, int n_in,
                              void* d_out, int out_size) {
    const float* x     = (const float*)d_in[0];
    const float* gamma = (const float*)d_in[1];
    const float* beta  = (const float*)d_in[2];
    const float* Wqkv  = (const float*)d_in[3];
    const float* Wout  = (const float*)d_in[4];
    const float* bout  = (const float*)d_in[5];
    const float* rel   = (const float*)d_in[6];
    const int*   tmask = (const int*)d_in[7];
    float* out = (float*)d_out;

    ln_stats_kernel<<<(BB * NN) / 8, 256>>>(x);
    qkv_gemm_kernel<<<dim3(QKVC / 128, (BB * NN) / 128), 256>>>(x, gamma, beta, Wqkv);

    cudaFuncSetAttribute(flash_mma_kernel, cudaFuncAttributeMaxDynamicSharedMemorySize, FLASH_SMEM);
    flash_mma_kernel<<<dim3(NN / 128, BB * HH), 256, FLASH_SMEM>>>(rel, tmask);

    out_gemm_kernel<<<dim3(DD / 128, (BB * NN) / 128), 256>>>(Wout, bout, out);
}

// round 6
// speedup vs baseline: 2.8041x; 1.3962x over previous
#include <cuda_runtime.h>
#include <math.h>
#include <stdint.h>

#define BB 4
#define NN 2048
#define DD 512
#define HH 8
#define DH 64
#define HD 512        // HH*DH
#define QKVC 1536     // 3*HH*DH
#define MAXREL 200

// ---- scratch (static device globals; no allocation allowed) ----
__device__ float g_xn[BB * NN * DD];        // LN output, tf32-rounded
__device__ float g_wqkv[DD * QKVC];         // tf32-rounded weights
__device__ float g_wout[HD * DD];
__device__ float g_q[BB * HH * NN * DH];    // [b,h,n,d]  tf32, pre-scaled
__device__ float g_k[BB * HH * NN * DH];    // [b,h,n,d]  tf32
__device__ float g_vT[BB * HH * DH * NN];   // [b,h,d,n]  tf32
__device__ float g_attn[BB * NN * HD];      // tf32-rounded

__device__ __forceinline__ float to_tf32(float x) {
    float r;
    asm("cvt.rna.tf32.f32 %0, %1;" : "=f"(r) : "f"(x));
    return r;
}

__device__ __forceinline__ void cp16(uint32_t s, const void* g) {
    asm volatile("cp.async.ca.shared.global [%0], [%1], 16;" :: "r"(s), "l"(g));
}
#define CP_COMMIT()  asm volatile("cp.async.commit_group;")
#define CP_WAIT(N)   asm volatile("cp.async.wait_group %0;" :: "n"(N))

#define MMA_TF32(d, a0,a1,a2,a3, b0,b1)                                        \
    asm volatile("mma.sync.aligned.m16n8k8.row.col.f32.tf32.tf32.f32 "         \
        "{%0,%1,%2,%3},{%4,%5,%6,%7},{%8,%9},{%0,%1,%2,%3};"                   \
        : "+f"((d)[0]), "+f"((d)[1]), "+f"((d)[2]), "+f"((d)[3])               \
        : "r"(a0), "r"(a1), "r"(a2), "r"(a3), "r"(b0), "r"(b1))

// ================= prep: rna-round weights to tf32 =================
__global__ __launch_bounds__(256) void round_w_kernel(const float* __restrict__ Wqkv,
                                                      const float* __restrict__ Wout) {
    int i = blockIdx.x * blockDim.x + threadIdx.x;   // float4 index
    const int nq4 = DD * QKVC / 4;                   // 196608
    const int no4 = HD * DD / 4;                     // 65536
    if (i < nq4) {
        float4 v = ((const float4*)Wqkv)[i];
        ((float4*)g_wqkv)[i] = make_float4(to_tf32(v.x), to_tf32(v.y), to_tf32(v.z), to_tf32(v.w));
    } else if (i < nq4 + no4) {
        int j = i - nq4;
        float4 v = ((const float4*)Wout)[j];
        ((float4*)g_wout)[j] = make_float4(to_tf32(v.x), to_tf32(v.y), to_tf32(v.z), to_tf32(v.w));
    }
}

// ================= LayerNorm: one warp per row, writes tf32 xn =================
__global__ __launch_bounds__(256) void ln_kernel(const float* __restrict__ x,
                                                 const float* __restrict__ gamma,
                                                 const float* __restrict__ beta) {
    int warp = (blockIdx.x * blockDim.x + threadIdx.x) >> 5;
    int lane = threadIdx.x & 31;
    if (warp >= BB * NN) return;
    const float4* row = reinterpret_cast<const float4*>(x + (size_t)warp * DD);
    float4 v[4];
    float s = 0.f, ss = 0.f;
#pragma unroll
    for (int i = 0; i < 4; ++i) {
        v[i] = row[lane + i * 32];
        s  += v[i].x + v[i].y + v[i].z + v[i].w;
        ss += v[i].x * v[i].x + v[i].y * v[i].y + v[i].z * v[i].z + v[i].w * v[i].w;
    }
#pragma unroll
    for (int off = 16; off; off >>= 1) {
        s  += __shfl_xor_sync(0xffffffffu, s,  off);
        ss += __shfl_xor_sync(0xffffffffu, ss, off);
    }
    float mu = s * (1.0f / DD);
    float rs = rsqrtf(ss * (1.0f / DD) - mu * mu + 1e-5f);
    float4* dst = reinterpret_cast<float4*>(g_xn + (size_t)warp * DD);
#pragma unroll
    for (int i = 0; i < 4; ++i) {
        int c = lane + i * 32;
        float4 gm = ((const float4*)gamma)[c];
        float4 be = ((const float4*)beta)[c];
        float4 o;
        o.x = to_tf32((v[i].x - mu) * rs * gm.x + be.x);
        o.y = to_tf32((v[i].y - mu) * rs * gm.y + be.y);
        o.z = to_tf32((v[i].z - mu) * rs * gm.z + be.z);
        o.w = to_tf32((v[i].w - mu) * rs * gm.w + be.w);
        dst[c] = o;
    }
}

// ========== shared tf32 GEMM skeleton: 128x128x16, 8 warps (4m x 2n), 32x64 warp tile ==========
// smem floats: As[2][128][20] @0 (buf stride 2560), Bs[2][16][136] @5120 (buf stride 2176)
#define GA(buf, r, c)  ((buf) * 2560 + (r) * 20 + (c))
#define GB(buf, r, c)  (5120 + (buf) * 2176 + (r) * 136 + (c))

#define GEMM_LOADA(buf, Ap, lda, k0)                                           \
    {                                                                          \
        _Pragma("unroll")                                                      \
        for (int i = 0; i < 2; ++i) {                                          \
            int idx = tid + i * 256;                                           \
            int r = idx >> 2, c = (idx & 3) * 4;                               \
            cp16(smb + GA(buf, r, c) * 4, (Ap) + (size_t)(m0 + r) * (lda) + (k0) + c); \
        }                                                                      \
    }
#define GEMM_LOADB(buf, Bp, ldb, k0)                                           \
    {                                                                          \
        _Pragma("unroll")                                                      \
        for (int i = 0; i < 2; ++i) {                                          \
            int idx = tid + i * 256;                                           \
            int r = idx >> 5, c = (idx & 31) * 4;                              \
            cp16(smb + GB(buf, r, c) * 4, (Bp) + (size_t)((k0) + r) * (ldb) + n0 + c); \
        }                                                                      \
    }

#define GEMM_MAIN(Ap, lda, Bp, ldb, KDIM)                                      \
    float acc[2][8][4] = {};                                                   \
    GEMM_LOADA(0, Ap, lda, 0);                                                 \
    GEMM_LOADB(0, Bp, ldb, 0);                                                 \
    CP_COMMIT();                                                               \
    for (int k0 = 0; k0 < (KDIM); k0 += 16) {                                  \
        int buf = (k0 >> 4) & 1;                                               \
        if (k0 > 0) __syncthreads();                                           \
        if (k0 + 16 < (KDIM)) {                                                \
            GEMM_LOADA(buf ^ 1, Ap, lda, k0 + 16);                             \
            GEMM_LOADB(buf ^ 1, Bp, ldb, k0 + 16);                             \
            CP_COMMIT();                                                       \
            CP_WAIT(1);                                                        \
        } else {                                                               \
            CP_WAIT(0);                                                        \
        }                                                                      \
        __syncthreads();                                                       \
        _Pragma("unroll")                                                      \
        for (int ks = 0; ks < 2; ++ks) {                                       \
            uint32_t af[2][4];                                                 \
            _Pragma("unroll")                                                  \
            for (int mi = 0; mi < 2; ++mi) {                                   \
                int r = wm + mi * 16 + g;                                      \
                af[mi][0] = __float_as_uint(sm[GA(buf, r,     ks * 8 + tig)]); \
                af[mi][1] = __float_as_uint(sm[GA(buf, r + 8, ks * 8 + tig)]); \
                af[mi][2] = __float_as_uint(sm[GA(buf, r,     ks * 8 + tig + 4)]); \
                af[mi][3] = __float_as_uint(sm[GA(buf, r + 8, ks * 8 + tig + 4)]); \
            }                                                                  \
            _Pragma("unroll")                                                  \
            for (int ni = 0; ni < 8; ++ni) {                                   \
                int cb = wn + ni * 8 + g;                                      \
                uint32_t b0 = __float_as_uint(sm[GB(buf, ks * 8 + tig,     cb)]); \
                uint32_t b1 = __float_as_uint(sm[GB(buf, ks * 8 + tig + 4, cb)]); \
                MMA_TF32(acc[0][ni], af[0][0], af[0][1], af[0][2], af[0][3], b0, b1); \
                MMA_TF32(acc[1][ni], af[1][0], af[1][1], af[1][2], af[1][3], b0, b1); \
            }                                                                  \
        }                                                                      \
    }

// ================= QKV GEMM (tf32 MMA): xn[8192,512] x Wqkv[512,1536] =================
__global__ __launch_bounds__(256, 2) void qkv_mma_kernel() {
    __shared__ float sm[9472];
    uint32_t smb = (uint32_t)__cvta_generic_to_shared(sm);
    int tid = threadIdx.x;
    int lane = tid & 31, wid = tid >> 5;
    int g = lane >> 2, tig = lane & 3;
    int wm = (wid >> 1) * 32, wn = (wid & 1) * 64;
    int m0 = blockIdx.y * 128, n0 = blockIdx.x * 128;

    GEMM_MAIN(g_xn, DD, g_wqkv, QKVC, DD);

    // epilogue: scatter tf32 Q(scaled)/K -> [b,h,n,d]; V -> [b,h,d,n]
#pragma unroll
    for (int ni = 0; ni < 8; ++ni) {
        int c = n0 + wn + ni * 8 + 2 * tig;
        int part = c >> 9, w = c & 511;
        int h = w >> 6, dd = w & 63;
#pragma unroll
        for (int mi = 0; mi < 2; ++mi) {
#pragma unroll
            for (int half = 0; half < 2; ++half) {
                int r = m0 + wm + mi * 16 + g + half * 8;
                int b = r >> 11, n = r & (NN - 1);
                size_t bh = (size_t)(b * HH + h);
                float v0 = acc[mi][ni][half * 2 + 0];
                float v1 = acc[mi][ni][half * 2 + 1];
                if (part == 0) {
                    *(float2*)&g_q[(bh * NN + n) * DH + dd] =
                        make_float2(to_tf32(v0 * 0.125f), to_tf32(v1 * 0.125f));
                } else if (part == 1) {
                    *(float2*)&g_k[(bh * NN + n) * DH + dd] =
                        make_float2(to_tf32(v0), to_tf32(v1));
                } else {
                    g_vT[(bh * DH + dd) * NN + n]     = to_tf32(v0);
                    g_vT[(bh * DH + dd + 1) * NN + n] = to_tf32(v1);
                }
            }
        }
    }
}

// ================= Out GEMM (tf32 MMA): attn[8192,512] x Wout[512,512] + bias =================
__global__ __launch_bounds__(256, 2) void out_mma_kernel(const float* __restrict__ bout,
                                                         float* __restrict__ out) {
    __shared__ float sm[9472];
    uint32_t smb = (uint32_t)__cvta_generic_to_shared(sm);
    int tid = threadIdx.x;
    int lane = tid & 31, wid = tid >> 5;
    int g = lane >> 2, tig = lane & 3;
    int wm = (wid >> 1) * 32, wn = (wid & 1) * 64;
    int m0 = blockIdx.y * 128, n0 = blockIdx.x * 128;

    GEMM_MAIN(g_attn, HD, g_wout, DD, HD);

#pragma unroll
    for (int ni = 0; ni < 8; ++ni) {
        int c = n0 + wn + ni * 8 + 2 * tig;
        float2 bo = *(const float2*)&bout[c];
#pragma unroll
        for (int mi = 0; mi < 2; ++mi) {
#pragma unroll
            for (int half = 0; half < 2; ++half) {
                int r = m0 + wm + mi * 16 + g + half * 8;
                *(float2*)&out[(size_t)r * DD + c] =
                    make_float2(acc[mi][ni][half * 2 + 0] + bo.x,
                                acc[mi][ni][half * 2 + 1] + bo.y);
            }
        }
    }
}

// ================= Flash attention with tf32 mma.sync =================
#define FS_QS   0
#define FS_KS   8704
#define FS_VS   13056
#define FS_STG  8704
#define FS_PS   26112
#define FS_TOT  34816
#define FLASH_SMEM (FS_TOT * 4)
#define NT_TILES (NN / 64)

__global__ __launch_bounds__(256, 1) void flash_mma_kernel(const float* __restrict__ rel_table,
                                                           const int* __restrict__ tmask) {
    extern __shared__ float sm[];
    uint32_t smb = (uint32_t)__cvta_generic_to_shared(sm);

    int tid  = threadIdx.x;
    int lane = tid & 31, wid = tid >> 5;
    int g   = lane >> 2;
    int tig = lane & 3;
    int bh = blockIdx.y;
    int q0 = blockIdx.x * 128;
    const float* Q  = g_q  + (size_t)bh * NN * DH;
    const float* K  = g_k  + (size_t)bh * NN * DH;
    const float* Vt = g_vT + (size_t)bh * DH * NN;

    int lr = tid >> 4;
    int lc = (tid & 15) * 4;

#pragma unroll
    for (int i = 0; i < 8; ++i) {
        int r = lr + i * 16;
        cp16(smb + (FS_QS + r * 68 + lc) * 4, Q + (size_t)(q0 + r) * DH + lc);
    }
#pragma unroll
    for (int i = 0; i < 4; ++i) {
        int r = lr + i * 16;
        cp16(smb + (FS_KS + r * 68 + lc) * 4, K + (size_t)r * DH + lc);
    }
#pragma unroll
    for (int i = 0; i < 4; ++i) {
        int r = lr + i * 16;
        cp16(smb + (FS_VS + r * 68 + lc) * 4, Vt + (size_t)r * NN + lc);
    }
    CP_COMMIT();

    float oa[8][4] = {};
    float mi[2] = {-INFINITY, -INFINITY};
    float li[2] = {0.f, 0.f};

    const int m_row = wid * 16 + g;
    const float* qb = sm + FS_QS + m_row * 68 + tig;

    for (int t = 0; t < NT_TILES; ++t) {
        int cur = t & 1;
        int k0 = t * 64;
        if (t > 0) __syncthreads();
        if (t + 1 < NT_TILES) {
            int nxt = cur ^ 1;
#pragma unroll
            for (int i = 0; i < 4; ++i) {
                int r = lr + i * 16;
                cp16(smb + (FS_KS + nxt * FS_STG + r * 68 + lc) * 4,
                     K + (size_t)(k0 + 64 + r) * DH + lc);
            }
#pragma unroll
            for (int i = 0; i < 4; ++i) {
                int r = lr + i * 16;
                cp16(smb + (FS_VS + nxt * FS_STG + r * 68 + lc) * 4,
                     Vt + (size_t)r * NN + k0 + 64 + lc);
            }
            CP_COMMIT();
            CP_WAIT(1);
        } else {
            CP_WAIT(0);
        }
        __syncthreads();

        const float* kb = sm + FS_KS + cur * FS_STG + g * 68 + tig;
        const float* vb = sm + FS_VS + cur * FS_STG + g * 68 + tig;

        float sa[8][4] = {};
#pragma unroll
        for (int ks = 0; ks < 8; ++ks) {
            uint32_t a0 = __float_as_uint(qb[ks * 8]);
            uint32_t a1 = __float_as_uint(qb[8 * 68 + ks * 8]);
            uint32_t a2 = __float_as_uint(qb[ks * 8 + 4]);
            uint32_t a3 = __float_as_uint(qb[8 * 68 + ks * 8 + 4]);
#pragma unroll
            for (int nt = 0; nt < 8; ++nt) {
                uint32_t b0 = __float_as_uint(kb[nt * 8 * 68 + ks * 8]);
                uint32_t b1 = __float_as_uint(kb[nt * 8 * 68 + ks * 8 + 4]);
                MMA_TF32(sa[nt], a0, a1, a2, a3, b0, b1);
            }
        }

#pragma unroll
        for (int ri = 0; ri < 2; ++ri) {
            int rl = m_row + ri * 8;
            int rg = q0 + rl;
            const int2* mp = (const int2*)(tmask + (size_t)rg * NN + k0);
            float mloc = -INFINITY;
#pragma unroll
            for (int nt = 0; nt < 8; ++nt) {
                int cc = nt * 8 + 2 * tig;
                int2 mm = mp[nt * 4 + tig];
                int cg = k0 + cc;
                int rel0 = min(max(rg - cg,     -(MAXREL - 1)), MAXREL - 1) + (MAXREL - 1);
                int rel1 = min(max(rg - cg - 1, -(MAXREL - 1)), MAXREL - 1) + (MAXREL - 1);
                float v0 = sa[nt][ri * 2 + 0] + __ldg(&rel_table[rel0]);
                float v1 = sa[nt][ri * 2 + 1] + __ldg(&rel_table[rel1]);
                v0 = (mm.x == 0) ? -1e9f : v0;
                v1 = (mm.y == 0) ? -1e9f : v1;
                sa[nt][ri * 2 + 0] = v0;
                sa[nt][ri * 2 + 1] = v1;
                mloc = fmaxf(mloc, fmaxf(v0, v1));
            }
            mloc = fmaxf(mloc, __shfl_xor_sync(0xffffffffu, mloc, 1));
            mloc = fmaxf(mloc, __shfl_xor_sync(0xffffffffu, mloc, 2));
            float mnew = fmaxf(mi[ri], mloc);
            float f = __expf(mi[ri] - mnew);
            float sum = 0.f;
            float2* psr = (float2*)(sm + FS_PS + rl * 68 + 2 * tig);
#pragma unroll
            for (int nt = 0; nt < 8; ++nt) {
                float e0 = to_tf32(__expf(sa[nt][ri * 2 + 0] - mnew));
                float e1 = to_tf32(__expf(sa[nt][ri * 2 + 1] - mnew));
                sum += e0 + e1;
                psr[nt * 4] = make_float2(e0, e1);
            }
            sum += __shfl_xor_sync(0xffffffffu, sum, 1);
            sum += __shfl_xor_sync(0xffffffffu, sum, 2);
            li[ri] = li[ri] * f + sum;
            mi[ri] = mnew;
#pragma unroll
            for (int nt = 0; nt < 8; ++nt) {
                oa[nt][ri * 2 + 0] *= f;
                oa[nt][ri * 2 + 1] *= f;
            }
        }
        __syncwarp();

        const float* pb = sm + FS_PS + m_row * 68 + tig;
#pragma unroll
        for (int ks = 0; ks < 8; ++ks) {
            uint32_t a0 = __float_as_uint(pb[ks * 8]);
            uint32_t a1 = __float_as_uint(pb[8 * 68 + ks * 8]);
            uint32_t a2 = __float_as_uint(pb[ks * 8 + 4]);
            uint32_t a3 = __float_as_uint(pb[8 * 68 + ks * 8 + 4]);
#pragma unroll
            for (int nt = 0; nt < 8; ++nt) {
                uint32_t b0 = __float_as_uint(vb[nt * 8 * 68 + ks * 8]);
                uint32_t b1 = __float_as_uint(vb[nt * 8 * 68 + ks * 8 + 4]);
                MMA_TF32(oa[nt], a0, a1, a2, a3, b0, b1);
            }
        }
    }

    int b = bh >> 3, h = bh & 7;
    float inv0 = 1.0f / li[0], inv1 = 1.0f / li[1];
#pragma unroll
    for (int nt = 0; nt < 8; ++nt) {
        int col = h * DH + nt * 8 + 2 * tig;
        int r0 = q0 + m_row;
        *(float2*)&g_attn[((size_t)(b * NN + r0)) * HD + col] =
            make_float2(to_tf32(oa[nt][0] * inv0), to_tf32(oa[nt][1] * inv0));
        *(float2*)&g_attn[((size_t)(b * NN + r0 + 8)) * HD + col] =
            make_float2(to_tf32(oa[nt][2] * inv1), to_tf32(oa[nt][3] * inv1));
    }
}

extern "C" void kernel_launch(void* const* d_in, const int* in_sizes, int n_in,
                              void* d_out, int out_size) {
    const float* x     = (const float*)d_in[0];
    const float* gamma = (const float*)d_in[1];
    const float* beta  = (const float*)d_in[2];
    const float* Wqkv  = (const float*)d_in[3];
    const float* Wout  = (const float*)d_in[4];
    const float* bout  = (const float*)d_in[5];
    const float* rel   = (const float*)d_in[6];
    const int*   tmask = (const int*)d_in[7];
    float* out = (float*)d_out;

    round_w_kernel<<<(DD * QKVC / 4 + HD * DD / 4 + 255) / 256, 256>>>(Wqkv, Wout);
    ln_kernel<<<(BB * NN) / 8, 256>>>(x, gamma, beta);
    qkv_mma_kernel<<<dim3(QKVC / 128, (BB * NN) / 128), 256>>>();

    cudaFuncSetAttribute(flash_mma_kernel, cudaFuncAttributeMaxDynamicSharedMemorySize, FLASH_SMEM);
    flash_mma_kernel<<<dim3(NN / 128, BB * HH), 256, FLASH_SMEM>>>(rel, tmask);

    out_mma_kernel<<<dim3(DD / 128, (BB * NN) / 128), 256>>>(bout, out);
}